// round 13
// baseline (speedup 1.0000x reference)
#include <cuda_runtime.h>
#include <cuda_fp16.h>
#include <cstdint>
#include <math.h>

#define BATCH 96
#define NQ 196
#define NR 77
#define DIM 512
#define KC 32                  // k elements per chunk
#define NCHUNK (DIM / KC)      // 16
#define NPAD 80
#define ROWB 80                // row stride bytes (64 data + 16 pad, conflict-free)
#define NTILES 3               // m-tiles: 96 + 96 + (compacted 4-row tail)

// ---------------- device scratch ----------------
__device__ __half g_ih0[BATCH * NQ * DIM];
__device__ __half g_ih1[BATCH * NQ * DIM];
__device__ __half g_th0[BATCH * NR * DIM];
__device__ __half g_th1[BATCH * NR * DIM];
__device__ float g_rowsum_part[NTILES * BATCH * BATCH];          // [mt][b][c]
__device__ float g_colmax_part[NTILES * BATCH * BATCH * NPAD];   // [mt][c][b][r]
__device__ float g_i2t[BATCH * BATCH];
__device__ float g_t2i[BATCH * BATCH];
__device__ float g_contrib[2 * BATCH];

// ---------------- PTX helpers (base sm_103 ISA only) ----------------
__device__ __forceinline__ uint32_t smem_u32(const void* p) {
    uint32_t a;
    asm("{ .reg .u64 t; cvta.to.shared.u64 t, %1; cvt.u32.u64 %0, t; }" : "=r"(a) : "l"(p));
    return a;
}
#define CP_ASYNC16(sa, gp, sz) \
    asm volatile("cp.async.cg.shared.global [%0], [%1], 16, %2;" \
        :: "r"(sa), "l"(gp), "r"(sz) : "memory")
#define CP_COMMIT()  asm volatile("cp.async.commit_group;" ::: "memory")
#define CP_WAIT1()   asm volatile("cp.async.wait_group 1;" ::: "memory")

#define LDSM_X4(r0, r1, r2, r3, a) \
    asm volatile("ldmatrix.sync.aligned.m8n8.x4.shared.b16 {%0,%1,%2,%3}, [%4];" \
        : "=r"(r0), "=r"(r1), "=r"(r2), "=r"(r3) : "r"(a))

// fp16 inputs, fp32 accumulator (main pass)
#define MMA_F32ACC(d, a0, a1, a2, a3, b0, b1) \
    asm volatile("mma.sync.aligned.m16n8k16.row.col.f32.f16.f16.f32 " \
        "{%0,%1,%2,%3}, {%4,%5,%6,%7}, {%8,%9}, {%0,%1,%2,%3};" \
        : "+f"((d)[0]), "+f"((d)[1]), "+f"((d)[2]), "+f"((d)[3]) \
        : "r"(a0), "r"(a1), "r"(a2), "r"(a3), "r"(b0), "r"(b1))

// fp16 inputs, fp16 accumulator (cross passes; 2x rate if HW supports)
#define MMA_F16ACC(d, a0, a1, a2, a3, b0, b1) \
    asm volatile("mma.sync.aligned.m16n8k16.row.col.f16.f16.f16.f16 " \
        "{%0,%1}, {%2,%3,%4,%5}, {%6,%7}, {%0,%1};" \
        : "+r"((d)[0]), "+r"((d)[1]) \
        : "r"(a0), "r"(a1), "r"(a2), "r"(a3), "r"(b0), "r"(b1))

// ===== precompute: split fp32 into fp16 hi (h0) and residual (h1) =====
__global__ void fg_split_kernel(const float* __restrict__ src,
                                __half* __restrict__ h0,
                                __half* __restrict__ h1, int n)
{
    int i = blockIdx.x * blockDim.x + threadIdx.x;
    if (i < n) {
        float x = src[i];
        __half h = __float2half(x);
        h0[i] = h;
        h1[i] = __float2half(x - __half2float(h));
    }
}

// ======================================================================
// fp16-split (main f32acc + 2 cross f16acc) MMA kernel.
// CTA tile: 96 x 160 (TWO texts). Warps: 2 (M) x 2 (N); each N-warp owns
// ONE FULL text (80 cols).
// TAIL=false: blockIdx.x = image, rows mt*96..mt*96+95 of that image.
// TAIL=true : blockIdx.x = tile (0..3); row r -> image tile*24 + r/4,
//             token 192 + r%4  (compacted 4-row tails of 24 images).
// ======================================================================
template <bool TAIL>
__global__ __launch_bounds__(128, 2) void fg_mma_kernel(int mt_base)
{
    constexpr int MROWS = 96;
    constexpr int MWARPS = 2;
    constexpr int NT   = 128;
    constexpr int MW   = 48;
    constexpr int MF   = 3;
    constexpr int A_SZ = MROWS * ROWB;       // per part
    constexpr int B_SZ = 2 * NPAD * ROWB;    // 12800 per part (two texts)
    constexpr int STAGE = 2 * A_SZ + 2 * B_SZ;

    extern __shared__ char smem_raw[];
    __shared__ float scmax[MWARPS][2][NPAD];
    __shared__ float swsum[NT / 32];

    const uint32_t raw_u  = smem_u32(smem_raw);
    const uint32_t tile_u = (raw_u + 1023u) & ~1023u;

    const int tid = threadIdx.x;
    const int wid = tid >> 5;
    const int lid = tid & 31;
    const int wn = wid & 1;           // text within pair
    const int wm = wid >> 1;          // 0..1
    const int g  = lid >> 3;
    const int r  = lid & 7;

    const int bx   = blockIdx.x;      // image (main) or tile (tail)
    const int cg   = blockIdx.y;
    const int mt   = mt_base + blockIdx.z;

    const size_t Abase = TAIL ? 0 : ((size_t)bx * NQ + mt * 96) * DIM;
    const size_t Tbase = (size_t)(cg * 2) * NR * DIM;

    float acc[MF][10][4];
#pragma unroll
    for (int mf = 0; mf < MF; ++mf)
#pragma unroll
        for (int fn = 0; fn < 10; ++fn)
#pragma unroll
            for (int cc = 0; cc < 4; ++cc) acc[mf][fn][cc] = 0.0f;

    // ---------------- staging ----------------
    auto stage = [&](int ci, int buf) {
        const int k0 = ci * KC;
        const uint32_t base = tile_u + buf * STAGE;
        // A: 96 rows x 4 slots x {h0,h1} = 768 ops
#pragma unroll
        for (int i = 0; i < (MROWS * 8) / NT; ++i) {
            int idx = tid + i * NT;
            int arr = (idx >= MROWS * 4) ? 1 : 0;
            int rem = idx - arr * MROWS * 4;
            int row = rem >> 2, u = rem & 3;
            size_t off;
            if (TAIL) {
                int img = bx * 24 + (row >> 2);
                int q   = 192 + (row & 3);
                off = ((size_t)img * NQ + q) * DIM + k0 + u * 8;
            } else {
                off = Abase + (size_t)row * DIM + k0 + u * 8;
            }
            const __half* sp = (arr ? g_ih1 : g_ih0) + off;
            uint32_t sa = base + arr * A_SZ + row * ROWB + u * 16;
            CP_ASYNC16(sa, sp, 16u);
        }
        // B: 160 rows (2 texts x 80) x 4 slots x {h0,h1} = 1280 ops
#pragma unroll
        for (int i = 0; i < 1280 / NT; ++i) {
            int idx = tid + i * NT;
            int arr = (idx >= 640) ? 1 : 0;
            int rem = idx - arr * 640;
            int row = rem >> 2, u = rem & 3;
            int tg = row / NPAD, rr = row - tg * NPAD;
            int crr = rr < NR ? rr : 0;
            const __half* sp = (arr ? g_th1 : g_th0) + Tbase + ((size_t)tg * NR + crr) * DIM + k0 + u * 8;
            uint32_t sz = (rr < NR) ? 16u : 0u;
            uint32_t sa = base + 2 * A_SZ + arr * B_SZ + row * ROWB + u * 16;
            CP_ASYNC16(sa, sp, sz);
        }
        CP_COMMIT();
    };

    stage(0, 0);
    stage(1, 1);

    // per-lane ldmatrix offsets (validated lane maps)
    const uint32_t a_row = (uint32_t)((wm * MW + (g & 1) * 8 + r) * ROWB);
    const uint32_t a_ub  = (uint32_t)(g >> 1);
    const uint32_t b_row = (uint32_t)((wn * NPAD + (g >> 1) * 8 + r) * ROWB);
    const uint32_t b_ub  = (uint32_t)(g & 1);

    // ---------------- main loop ----------------
    for (int ci = 0; ci < NCHUNK; ++ci) {
        const int buf = ci & 1;
        CP_WAIT1();
        __syncthreads();

        const uint32_t sA = tile_u + buf * STAGE;
        const uint32_t sB = sA + 2 * A_SZ;

        // per-chunk f16 cross accumulators (folded to f32 at chunk end)
        uint32_t xacc[MF][10][2];
#pragma unroll
        for (int mf = 0; mf < MF; ++mf)
#pragma unroll
            for (int fn = 0; fn < 10; ++fn) {
                xacc[mf][fn][0] = 0u;
                xacc[mf][fn][1] = 0u;
            }

#pragma unroll
        for (int ks = 0; ks < 2; ++ks) {
            uint32_t a0[MF][4], a1[MF][4];
            const uint32_t a_ch = (uint32_t)(ks * 32) + a_ub * 16;
#pragma unroll
            for (int mf = 0; mf < MF; ++mf) {
                uint32_t ad = sA + a_row + (uint32_t)(mf * 16 * ROWB) + a_ch;
                LDSM_X4(a0[mf][0], a0[mf][1], a0[mf][2], a0[mf][3], ad);
                LDSM_X4(a1[mf][0], a1[mf][1], a1[mf][2], a1[mf][3], ad + A_SZ);
            }
            const uint32_t b_ch = (uint32_t)(ks * 32) + b_ub * 16;
#pragma unroll
            for (int p = 0; p < 5; ++p) {
                uint32_t bh[4], bl[4];
                uint32_t bd = sB + b_row + (uint32_t)(p * 16 * ROWB) + b_ch;
                LDSM_X4(bh[0], bh[1], bh[2], bh[3], bd);
                LDSM_X4(bl[0], bl[1], bl[2], bl[3], bd + B_SZ);
                // main pass: h0 x h0, f32 accum
#pragma unroll
                for (int mf = 0; mf < MF; ++mf)
                    MMA_F32ACC(acc[mf][2 * p],     a0[mf][0], a0[mf][1], a0[mf][2], a0[mf][3], bh[0], bh[1]);
#pragma unroll
                for (int mf = 0; mf < MF; ++mf)
                    MMA_F32ACC(acc[mf][2 * p + 1], a0[mf][0], a0[mf][1], a0[mf][2], a0[mf][3], bh[2], bh[3]);
                // cross passes: f16 accum
#pragma unroll
                for (int mf = 0; mf < MF; ++mf)
                    MMA_F16ACC(xacc[mf][2 * p],     a0[mf][0], a0[mf][1], a0[mf][2], a0[mf][3], bl[0], bl[1]);
#pragma unroll
                for (int mf = 0; mf < MF; ++mf)
                    MMA_F16ACC(xacc[mf][2 * p + 1], a0[mf][0], a0[mf][1], a0[mf][2], a0[mf][3], bl[2], bl[3]);
#pragma unroll
                for (int mf = 0; mf < MF; ++mf)
                    MMA_F16ACC(xacc[mf][2 * p],     a1[mf][0], a1[mf][1], a1[mf][2], a1[mf][3], bh[0], bh[1]);
#pragma unroll
                for (int mf = 0; mf < MF; ++mf)
                    MMA_F16ACC(xacc[mf][2 * p + 1], a1[mf][0], a1[mf][1], a1[mf][2], a1[mf][3], bh[2], bh[3]);
            }
        }

        // fold f16 cross accumulators into f32 accs
#pragma unroll
        for (int mf = 0; mf < MF; ++mf)
#pragma unroll
            for (int fn = 0; fn < 10; ++fn) {
                float2 lo = __half22float2(*(__half2*)&xacc[mf][fn][0]);
                float2 hi = __half22float2(*(__half2*)&xacc[mf][fn][1]);
                acc[mf][fn][0] += lo.x;
                acc[mf][fn][1] += lo.y;
                acc[mf][fn][2] += hi.x;
                acc[mf][fn][3] += hi.y;
            }

        __syncthreads();
        if (ci + 2 < NCHUNK) stage(ci + 2, buf);
        else                 CP_COMMIT();   // keep group parity
    }

    // ---------------- epilogue ----------------
    // acc (mf, fn, cc): row_l = wm*48 + mf*16 + (cc>=2)*8 + lid/4
    //                   col   = fn*8 + 2*(lid&3) + (cc&1)   (within text wn)
    const int c0b = 2 * (lid & 3);
    const int cdx = cg * 2 + wn;      // text index

    if (!TAIL) {
        float rsum = 0.0f;
#pragma unroll
        for (int mf = 0; mf < MF; ++mf) {
#pragma unroll
            for (int h = 0; h < 2; ++h) {
                float m = -INFINITY;
#pragma unroll
                for (int fn = 0; fn < 10; ++fn) {
                    int col = fn * 8 + c0b;
                    if (col < NR)     m = fmaxf(m, acc[mf][fn][h * 2 + 0]);
                    if (col + 1 < NR) m = fmaxf(m, acc[mf][fn][h * 2 + 1]);
                }
                m = fmaxf(m, __shfl_xor_sync(0xFFFFFFFFu, m, 1));
                m = fmaxf(m, __shfl_xor_sync(0xFFFFFFFFu, m, 2));
                if ((lid & 3) == 0) rsum += m;
            }
        }
#pragma unroll
        for (int off = 16; off > 0; off >>= 1)
            rsum += __shfl_xor_sync(0xFFFFFFFFu, rsum, off);
        if (lid == 0) swsum[wid] = rsum;

#pragma unroll
        for (int fn = 0; fn < 10; ++fn) {
#pragma unroll
            for (int cb = 0; cb < 2; ++cb) {
                float m = -INFINITY;
#pragma unroll
                for (int mf = 0; mf < MF; ++mf)
#pragma unroll
                    for (int h = 0; h < 2; ++h)
                        m = fmaxf(m, acc[mf][fn][h * 2 + cb]);
                m = fmaxf(m, __shfl_xor_sync(0xFFFFFFFFu, m, 4));
                m = fmaxf(m, __shfl_xor_sync(0xFFFFFFFFu, m, 8));
                m = fmaxf(m, __shfl_xor_sync(0xFFFFFFFFu, m, 16));
                if (lid < 4) scmax[wm][wn][fn * 8 + 2 * lid + cb] = m;
            }
        }
        __syncthreads();

        if (tid < 2) {
            float s = swsum[tid];
#pragma unroll
            for (int w = 1; w < MWARPS; ++w) s += swsum[w * 2 + tid];
            g_rowsum_part[((size_t)mt * BATCH + bx) * BATCH + cg * 2 + tid] = s;
        }
        for (int idx = tid; idx < 2 * NPAD; idx += NT) {
            int wn2 = idx / NPAD, col = idx - wn2 * NPAD;
            float m = scmax[0][wn2][col];
#pragma unroll
            for (int w = 1; w < MWARPS; ++w) m = fmaxf(m, scmax[w][wn2][col]);
            int c = cg * 2 + wn2;
            g_colmax_part[(((size_t)mt * BATCH + c) * BATCH + bx) * NPAD + col] = m;
        }
    } else {
        // -------- tail epilogue: per-4-row-group (= per image) reductions --------
#pragma unroll
        for (int mf = 0; mf < MF; ++mf) {
#pragma unroll
            for (int h = 0; h < 2; ++h) {
                float m = -INFINITY;
#pragma unroll
                for (int fn = 0; fn < 10; ++fn) {
                    int col = fn * 8 + c0b;
                    if (col < NR)     m = fmaxf(m, acc[mf][fn][h * 2 + 0]);
                    if (col + 1 < NR) m = fmaxf(m, acc[mf][fn][h * 2 + 1]);
                }
                m = fmaxf(m, __shfl_xor_sync(0xFFFFFFFFu, m, 1));
                m = fmaxf(m, __shfl_xor_sync(0xFFFFFFFFu, m, 2));
                m += __shfl_xor_sync(0xFFFFFFFFu, m, 4);
                m += __shfl_xor_sync(0xFFFFFFFFu, m, 8);
                if ((lid & 15) == 0) {
                    int group = mf * 4 + h * 2 + (lid >> 4);
                    int img = bx * 24 + wm * 12 + group;
                    g_rowsum_part[((size_t)mt * BATCH + img) * BATCH + cdx] = m;
                }
            }
        }
#pragma unroll
        for (int mf = 0; mf < MF; ++mf) {
#pragma unroll
            for (int h = 0; h < 2; ++h) {
#pragma unroll
                for (int fn = 0; fn < 10; ++fn) {
#pragma unroll
                    for (int cb = 0; cb < 2; ++cb) {
                        float v = acc[mf][fn][h * 2 + cb];
                        v = fmaxf(v, __shfl_xor_sync(0xFFFFFFFFu, v, 4));
                        v = fmaxf(v, __shfl_xor_sync(0xFFFFFFFFu, v, 8));
                        if (((lid >> 2) & 3) == 0) {
                            int group = mf * 4 + h * 2 + (lid >> 4);
                            int img = bx * 24 + wm * 12 + group;
                            int col = fn * 8 + c0b + cb;
                            if (col < NR)
                                g_colmax_part[(((size_t)mt * BATCH + cdx) * BATCH + img) * NPAD + col] = v;
                        }
                    }
                }
            }
        }
    }
}

// ===== combine partial tiles into logit matrices =====
__global__ void fg_combine_kernel()
{
    const int c = blockIdx.x;    // 96
    const int b = threadIdx.x;   // 96
    float rs = 0.f;
#pragma unroll
    for (int t = 0; t < NTILES; ++t)
        rs += g_rowsum_part[((size_t)t * BATCH + b) * BATCH + c];
    g_i2t[b * BATCH + c] = rs * (1.0f / NQ);

    const float* p0 = &g_colmax_part[(((size_t)0 * BATCH + c) * BATCH + b) * NPAD];
    const float* p1 = &g_colmax_part[(((size_t)1 * BATCH + c) * BATCH + b) * NPAD];
    const float* p2 = &g_colmax_part[(((size_t)2 * BATCH + c) * BATCH + b) * NPAD];
    float s = 0.f;
#pragma unroll
    for (int rr = 0; rr < NR; ++rr) s += fmaxf(fmaxf(p0[rr], p1[rr]), p2[rr]);
    g_t2i[c * BATCH + b] = s * (1.0f / NR);
}

// ===== per-row cross-entropy (one warp per row, 192 rows) =====
__global__ void fg_rowce_kernel()
{
    const int wid = threadIdx.x >> 5;
    const int lid = threadIdx.x & 31;
    const int row = blockIdx.x * 32 + wid;
    if (row >= 2 * BATCH) return;
    const int label = (row < BATCH) ? row : row - BATCH;
    const float* base = (row < BATCH) ? &g_i2t[row * BATCH] : &g_t2i[(row - BATCH) * BATCH];

    float v0 = base[lid], v1 = base[lid + 32], v2 = base[lid + 64];
    float m = fmaxf(v0, fmaxf(v1, v2));
#pragma unroll
    for (int off = 16; off > 0; off >>= 1)
        m = fmaxf(m, __shfl_xor_sync(0xFFFFFFFFu, m, off));
    float s = expf(v0 - m) + expf(v1 - m) + expf(v2 - m);
#pragma unroll
    for (int off = 16; off > 0; off >>= 1)
        s += __shfl_xor_sync(0xFFFFFFFFu, s, off);
    float lse = m + logf(s);
    int slot = label >> 5, src = label & 31;
    float mine = (slot == 0) ? v0 : ((slot == 1) ? v1 : v2);
    float dval = __shfl_sync(0xFFFFFFFFu, mine, src);
    if (lid == 0) g_contrib[row] = lse - dval;
}

__global__ void fg_final_kernel(float* __restrict__ out)
{
    __shared__ float sred[192];
    const int t = threadIdx.x;
    sred[t] = g_contrib[t];
    __syncthreads();
    if (t == 0) {
        float s = 0.f;
        for (int i = 0; i < 2 * BATCH; i++) s += sred[i];
        out[0] = s * (0.5f / BATCH);
    }
}

extern "C" void kernel_launch(void* const* d_in, const int* in_sizes, int n_in,
                              void* d_out, int out_size)
{
    const float* img;
    const float* txt;
    if (in_sizes[0] > in_sizes[1]) { img = (const float*)d_in[0]; txt = (const float*)d_in[1]; }
    else                           { img = (const float*)d_in[1]; txt = (const float*)d_in[0]; }
    float* out = (float*)d_out;

    constexpr int STAGE = 2 * (96 * ROWB) + 2 * (2 * NPAD * ROWB);   // 40960
    constexpr int SMEM  = 2 * STAGE + 1024;   // 82944 -> 2 CTAs/SM

    static int configured = 0;
    if (!configured) {
        cudaFuncSetAttribute(fg_mma_kernel<false>, cudaFuncAttributeMaxDynamicSharedMemorySize, SMEM);
        cudaFuncSetAttribute(fg_mma_kernel<true>,  cudaFuncAttributeMaxDynamicSharedMemorySize, SMEM);
        configured = 1;
    }

    // fp16 hi/lo split of both inputs
    {
        __half *ih0, *ih1, *th0, *th1;
        cudaGetSymbolAddress((void**)&ih0, g_ih0);
        cudaGetSymbolAddress((void**)&ih1, g_ih1);
        cudaGetSymbolAddress((void**)&th0, g_th0);
        cudaGetSymbolAddress((void**)&th1, g_th1);
        int ni = BATCH * NQ * DIM, nt = BATCH * NR * DIM;
        fg_split_kernel<<<(ni + 255) / 256, 256>>>(img, ih0, ih1, ni);
        fg_split_kernel<<<(nt + 255) / 256, 256>>>(txt, th0, th1, nt);
    }

    // m-tiles 0,1: rows 0-95, 96-191 (all valid).
    fg_mma_kernel<false><<<dim3(BATCH, BATCH / 2, 2), 128, SMEM>>>(0);
    // tail: rows 192-195 of all images, compacted 4 rows/image x 24 images/tile.
    fg_mma_kernel<true><<<dim3(4, BATCH / 2, 1), 128, SMEM>>>(2);
    fg_combine_kernel<<<BATCH, BATCH>>>();
    fg_rowce_kernel<<<6, 1024>>>();
    fg_final_kernel<<<1, 192>>>(out);
}

// round 14
// speedup vs baseline: 1.0167x; 1.0167x over previous
#include <cuda_runtime.h>
#include <cuda_bf16.h>
#include <cstdint>
#include <math.h>

#define BATCH 96
#define NQ 196
#define NR 77
#define DIM 512
#define KC 32                  // k elements per chunk
#define NCHUNK (DIM / KC)      // 16
#define NPAD 80
#define ROWB 80                // B row stride bytes (64 data + 16 pad, conflict-free)
#define NTILES 3               // m-tiles: 96 + 96 + (compacted 4-row tail)

// ---------------- device scratch ----------------
__device__ __nv_bfloat16 g_ib0[BATCH * NQ * DIM];
__device__ __nv_bfloat16 g_ib1[BATCH * NQ * DIM];
__device__ __nv_bfloat16 g_tb0[BATCH * NR * DIM];
__device__ __nv_bfloat16 g_tb1[BATCH * NR * DIM];
__device__ float g_rowsum_part[NTILES * BATCH * BATCH];          // [mt][b][c]
__device__ float g_colmax_part[NTILES * BATCH * BATCH * NPAD];   // [mt][c][b][r]
__device__ float g_i2t[BATCH * BATCH];
__device__ float g_t2i[BATCH * BATCH];
__device__ float g_contrib[2 * BATCH];

// ---------------- PTX helpers (base sm_103 ISA only) ----------------
__device__ __forceinline__ uint32_t smem_u32(const void* p) {
    uint32_t a;
    asm("{ .reg .u64 t; cvta.to.shared.u64 t, %1; cvt.u32.u64 %0, t; }" : "=r"(a) : "l"(p));
    return a;
}
#define CP_ASYNC16(sa, gp, sz) \
    asm volatile("cp.async.cg.shared.global [%0], [%1], 16, %2;" \
        :: "r"(sa), "l"(gp), "r"(sz) : "memory")
#define CP_COMMIT()  asm volatile("cp.async.commit_group;" ::: "memory")
#define CP_WAIT2()   asm volatile("cp.async.wait_group 2;" ::: "memory")

#define LDSM_X4(r0, r1, r2, r3, a) \
    asm volatile("ldmatrix.sync.aligned.m8n8.x4.shared.b16 {%0,%1,%2,%3}, [%4];" \
        : "=r"(r0), "=r"(r1), "=r"(r2), "=r"(r3) : "r"(a))

#define MMA_BF16(d, a0, a1, a2, a3, b0, b1) \
    asm volatile("mma.sync.aligned.m16n8k16.row.col.f32.bf16.bf16.f32 " \
        "{%0,%1,%2,%3}, {%4,%5,%6,%7}, {%8,%9}, {%0,%1,%2,%3};" \
        : "+f"((d)[0]), "+f"((d)[1]), "+f"((d)[2]), "+f"((d)[3]) \
        : "r"(a0), "r"(a1), "r"(a2), "r"(a3), "r"(b0), "r"(b1))

__device__ __forceinline__ uint32_t ldg32(const __nv_bfloat16* p) {
    return __ldg((const uint32_t*)p);
}

// ===== precompute: split fp32 into bf16 hi (b0) and residual (b1) =====
__global__ void fg_split_kernel(const float* __restrict__ src,
                                __nv_bfloat16* __restrict__ b0,
                                __nv_bfloat16* __restrict__ b1, int n)
{
    int i = blockIdx.x * blockDim.x + threadIdx.x;
    if (i < n) {
        float x = src[i];
        __nv_bfloat16 h = __float2bfloat16(x);
        b0[i] = h;
        b1[i] = __float2bfloat16(x - __bfloat162float(h));
    }
}

// ======================================================================
// bf16x2 (3-pass) MMA kernel. CTA tile: 96 x 160 (TWO texts).
// A operand: DIRECT LDG fragment loads (no smem round-trip).
// B operand: cp.async -> smem (3-stage) -> ldmatrix.
// Warps: 2 (M) x 2 (N); each N-warp owns ONE FULL text (80 cols).
// TAIL=false: blockIdx.x = image, rows mt*96..mt*96+95 of that image.
// TAIL=true : blockIdx.x = tile (0..3); row r -> image tile*24 + r/4,
//             token 192 + r%4  (compacted 4-row tails of 24 images).
// ======================================================================
template <bool TAIL>
__global__ __launch_bounds__(128, 2) void fg_mma_kernel(int mt_base)
{
    constexpr int MWARPS = 2;
    constexpr int NT   = 128;
    constexpr int MW   = 48;
    constexpr int MF   = 3;
    constexpr int B_SZ = 2 * NPAD * ROWB;    // 12800 per part (two texts)
    constexpr int STAGE = 2 * B_SZ;          // 25600 (b0 + b1 parts)

    extern __shared__ char smem_raw[];
    __shared__ float scmax[MWARPS][2][NPAD];
    __shared__ float swsum[NT / 32];

    const uint32_t raw_u  = smem_u32(smem_raw);
    const uint32_t tile_u = (raw_u + 1023u) & ~1023u;

    const int tid = threadIdx.x;
    const int wid = tid >> 5;
    const int lid = tid & 31;
    const int wn = wid & 1;           // text within pair
    const int wm = wid >> 1;          // 0..1
    const int g  = lid >> 3;
    const int r  = lid & 7;

    const int bx   = blockIdx.x;      // image (main) or tile (tail)
    const int cg   = blockIdx.y;
    const int mt   = mt_base + blockIdx.z;

    const size_t Tbase = (size_t)(cg * 2) * NR * DIM;

    // A fragment row -> global element offset (col 0) for this lane
    auto arow_off = [&](int row_l) -> size_t {
        if (TAIL) {
            int img = bx * 24 + (row_l >> 2);
            int q   = 192 + (row_l & 3);
            return ((size_t)img * NQ + q) * DIM;
        }
        return ((size_t)bx * NQ + mt * 96 + row_l) * DIM;
    };
    // 6 row offsets: [mf][0] = row wm*48+mf*16+lid/4, [mf][1] = +8
    size_t aoff[MF][2];
#pragma unroll
    for (int mf = 0; mf < MF; ++mf) {
        int r0 = wm * MW + mf * 16 + (lid >> 2);
        aoff[mf][0] = arow_off(r0);
        aoff[mf][1] = arow_off(r0 + 8);
    }
    const int acol = 2 * (lid & 3);   // lane's col-pair base within k16

    float acc[MF][10][4];
#pragma unroll
    for (int mf = 0; mf < MF; ++mf)
#pragma unroll
        for (int fn = 0; fn < 10; ++fn)
#pragma unroll
            for (int cc = 0; cc < 4; ++cc) acc[mf][fn][cc] = 0.0f;

    // ---------------- B staging (cp.async) ----------------
    auto stage = [&](int ci, int buf) {
        const int k0 = ci * KC;
        const uint32_t base = tile_u + buf * STAGE;
        // B: 160 rows (2 texts x 80) x 4 slots x {b0,b1} = 1280 ops
#pragma unroll
        for (int i = 0; i < 1280 / NT; ++i) {
            int idx = tid + i * NT;
            int arr = (idx >= 640) ? 1 : 0;
            int rem = idx - arr * 640;
            int row = rem >> 2, u = rem & 3;
            int tg = row / NPAD, rr = row - tg * NPAD;
            int crr = rr < NR ? rr : 0;
            const __nv_bfloat16* sp = (arr ? g_tb1 : g_tb0) + Tbase + ((size_t)tg * NR + crr) * DIM + k0 + u * 8;
            uint32_t sz = (rr < NR) ? 16u : 0u;
            uint32_t sa = base + arr * B_SZ + row * ROWB + u * 16;
            CP_ASYNC16(sa, sp, sz);
        }
        CP_COMMIT();
    };

    stage(0, 0);
    stage(1, 1);
    stage(2, 2);

    // per-lane ldmatrix offsets for B (validated lane maps)
    const uint32_t b_row = (uint32_t)((wn * NPAD + (g >> 1) * 8 + r) * ROWB);
    const uint32_t b_ub  = (uint32_t)(g & 1);

    // ---------------- main loop ----------------
    for (int ci = 0; ci < NCHUNK; ++ci) {
        const int buf = ci % 3;
        const int k0 = ci * KC;

        // A fragments for this chunk: direct LDG (independent of cp.async)
        // afr[part][mf][ks][4]: [0]=(r0,c), [1]=(r0+8,c), [2]=(r0,c+8), [3]=(r0+8,c+8)
        uint32_t afr0[MF][2][4], afr1[MF][2][4];
#pragma unroll
        for (int mf = 0; mf < MF; ++mf) {
#pragma unroll
            for (int ks = 0; ks < 2; ++ks) {
                size_t c0 = (size_t)(k0 + ks * 16 + acol);
                afr0[mf][ks][0] = ldg32(g_ib0 + aoff[mf][0] + c0);
                afr0[mf][ks][1] = ldg32(g_ib0 + aoff[mf][1] + c0);
                afr0[mf][ks][2] = ldg32(g_ib0 + aoff[mf][0] + c0 + 8);
                afr0[mf][ks][3] = ldg32(g_ib0 + aoff[mf][1] + c0 + 8);
                afr1[mf][ks][0] = ldg32(g_ib1 + aoff[mf][0] + c0);
                afr1[mf][ks][1] = ldg32(g_ib1 + aoff[mf][1] + c0);
                afr1[mf][ks][2] = ldg32(g_ib1 + aoff[mf][0] + c0 + 8);
                afr1[mf][ks][3] = ldg32(g_ib1 + aoff[mf][1] + c0 + 8);
            }
        }

        CP_WAIT2();
        __syncthreads();

        const uint32_t sB = tile_u + buf * STAGE;

#pragma unroll
        for (int ks = 0; ks < 2; ++ks) {
            const uint32_t b_ch = (uint32_t)(ks * 32) + b_ub * 16;
#pragma unroll
            for (int p = 0; p < 5; ++p) {
                uint32_t bh[4], bl[4];
                uint32_t bd = sB + b_row + (uint32_t)(p * 16 * ROWB) + b_ch;
                LDSM_X4(bh[0], bh[1], bh[2], bh[3], bd);
                LDSM_X4(bl[0], bl[1], bl[2], bl[3], bd + B_SZ);
#pragma unroll
                for (int mf = 0; mf < MF; ++mf)
                    MMA_BF16(acc[mf][2 * p],     afr0[mf][ks][0], afr0[mf][ks][1], afr0[mf][ks][2], afr0[mf][ks][3], bh[0], bh[1]);
#pragma unroll
                for (int mf = 0; mf < MF; ++mf)
                    MMA_BF16(acc[mf][2 * p + 1], afr0[mf][ks][0], afr0[mf][ks][1], afr0[mf][ks][2], afr0[mf][ks][3], bh[2], bh[3]);
#pragma unroll
                for (int mf = 0; mf < MF; ++mf)
                    MMA_BF16(acc[mf][2 * p],     afr0[mf][ks][0], afr0[mf][ks][1], afr0[mf][ks][2], afr0[mf][ks][3], bl[0], bl[1]);
#pragma unroll
                for (int mf = 0; mf < MF; ++mf)
                    MMA_BF16(acc[mf][2 * p + 1], afr0[mf][ks][0], afr0[mf][ks][1], afr0[mf][ks][2], afr0[mf][ks][3], bl[2], bl[3]);
#pragma unroll
                for (int mf = 0; mf < MF; ++mf)
                    MMA_BF16(acc[mf][2 * p],     afr1[mf][ks][0], afr1[mf][ks][1], afr1[mf][ks][2], afr1[mf][ks][3], bh[0], bh[1]);
#pragma unroll
                for (int mf = 0; mf < MF; ++mf)
                    MMA_BF16(acc[mf][2 * p + 1], afr1[mf][ks][0], afr1[mf][ks][1], afr1[mf][ks][2], afr1[mf][ks][3], bh[2], bh[3]);
            }
        }

        __syncthreads();
        if (ci + 3 < NCHUNK) stage(ci + 3, buf);
        else                 CP_COMMIT();   // keep group parity
    }

    // ---------------- epilogue ----------------
    // acc (mf, fn, cc): row_l = wm*48 + mf*16 + (cc>=2)*8 + lid/4
    //                   col   = fn*8 + 2*(lid&3) + (cc&1)   (within text wn)
    const int c0b = 2 * (lid & 3);
    const int cdx = cg * 2 + wn;      // text index

    if (!TAIL) {
        float rsum = 0.0f;
#pragma unroll
        for (int mf = 0; mf < MF; ++mf) {
#pragma unroll
            for (int h = 0; h < 2; ++h) {
                float m = -INFINITY;
#pragma unroll
                for (int fn = 0; fn < 10; ++fn) {
                    int col = fn * 8 + c0b;
                    if (col < NR)     m = fmaxf(m, acc[mf][fn][h * 2 + 0]);
                    if (col + 1 < NR) m = fmaxf(m, acc[mf][fn][h * 2 + 1]);
                }
                m = fmaxf(m, __shfl_xor_sync(0xFFFFFFFFu, m, 1));
                m = fmaxf(m, __shfl_xor_sync(0xFFFFFFFFu, m, 2));
                if ((lid & 3) == 0) rsum += m;
            }
        }
#pragma unroll
        for (int off = 16; off > 0; off >>= 1)
            rsum += __shfl_xor_sync(0xFFFFFFFFu, rsum, off);
        if (lid == 0) swsum[wid] = rsum;

#pragma unroll
        for (int fn = 0; fn < 10; ++fn) {
#pragma unroll
            for (int cb = 0; cb < 2; ++cb) {
                float m = -INFINITY;
#pragma unroll
                for (int mf = 0; mf < MF; ++mf)
#pragma unroll
                    for (int h = 0; h < 2; ++h)
                        m = fmaxf(m, acc[mf][fn][h * 2 + cb]);
                m = fmaxf(m, __shfl_xor_sync(0xFFFFFFFFu, m, 4));
                m = fmaxf(m, __shfl_xor_sync(0xFFFFFFFFu, m, 8));
                m = fmaxf(m, __shfl_xor_sync(0xFFFFFFFFu, m, 16));
                if (lid < 4) scmax[wm][wn][fn * 8 + 2 * lid + cb] = m;
            }
        }
        __syncthreads();

        if (tid < 2) {
            float s = swsum[tid];
#pragma unroll
            for (int w = 1; w < MWARPS; ++w) s += swsum[w * 2 + tid];
            g_rowsum_part[((size_t)mt * BATCH + bx) * BATCH + cg * 2 + tid] = s;
        }
        for (int idx = tid; idx < 2 * NPAD; idx += NT) {
            int wn2 = idx / NPAD, col = idx - wn2 * NPAD;
            float m = scmax[0][wn2][col];
#pragma unroll
            for (int w = 1; w < MWARPS; ++w) m = fmaxf(m, scmax[w][wn2][col]);
            int c = cg * 2 + wn2;
            g_colmax_part[(((size_t)mt * BATCH + c) * BATCH + bx) * NPAD + col] = m;
        }
    } else {
        // -------- tail epilogue: per-4-row-group (= per image) reductions --------
#pragma unroll
        for (int mf = 0; mf < MF; ++mf) {
#pragma unroll
            for (int h = 0; h < 2; ++h) {
                float m = -INFINITY;
#pragma unroll
                for (int fn = 0; fn < 10; ++fn) {
                    int col = fn * 8 + c0b;
                    if (col < NR)     m = fmaxf(m, acc[mf][fn][h * 2 + 0]);
                    if (col + 1 < NR) m = fmaxf(m, acc[mf][fn][h * 2 + 1]);
                }
                m = fmaxf(m, __shfl_xor_sync(0xFFFFFFFFu, m, 1));
                m = fmaxf(m, __shfl_xor_sync(0xFFFFFFFFu, m, 2));
                m += __shfl_xor_sync(0xFFFFFFFFu, m, 4);
                m += __shfl_xor_sync(0xFFFFFFFFu, m, 8);
                if ((lid & 15) == 0) {
                    int group = mf * 4 + h * 2 + (lid >> 4);
                    int img = bx * 24 + wm * 12 + group;
                    g_rowsum_part[((size_t)mt * BATCH + img) * BATCH + cdx] = m;
                }
            }
        }
#pragma unroll
        for (int mf = 0; mf < MF; ++mf) {
#pragma unroll
            for (int h = 0; h < 2; ++h) {
#pragma unroll
                for (int fn = 0; fn < 10; ++fn) {
#pragma unroll
                    for (int cb = 0; cb < 2; ++cb) {
                        float v = acc[mf][fn][h * 2 + cb];
                        v = fmaxf(v, __shfl_xor_sync(0xFFFFFFFFu, v, 4));
                        v = fmaxf(v, __shfl_xor_sync(0xFFFFFFFFu, v, 8));
                        if (((lid >> 2) & 3) == 0) {
                            int group = mf * 4 + h * 2 + (lid >> 4);
                            int img = bx * 24 + wm * 12 + group;
                            int col = fn * 8 + c0b + cb;
                            if (col < NR)
                                g_colmax_part[(((size_t)mt * BATCH + cdx) * BATCH + img) * NPAD + col] = v;
                        }
                    }
                }
            }
        }
    }
}

// ===== combine partial tiles into logit matrices =====
__global__ void fg_combine_kernel()
{
    const int c = blockIdx.x;    // 96
    const int b = threadIdx.x;   // 96
    float rs = 0.f;
#pragma unroll
    for (int t = 0; t < NTILES; ++t)
        rs += g_rowsum_part[((size_t)t * BATCH + b) * BATCH + c];
    g_i2t[b * BATCH + c] = rs * (1.0f / NQ);

    const float* p0 = &g_colmax_part[(((size_t)0 * BATCH + c) * BATCH + b) * NPAD];
    const float* p1 = &g_colmax_part[(((size_t)1 * BATCH + c) * BATCH + b) * NPAD];
    const float* p2 = &g_colmax_part[(((size_t)2 * BATCH + c) * BATCH + b) * NPAD];
    float s = 0.f;
#pragma unroll
    for (int rr = 0; rr < NR; ++rr) s += fmaxf(fmaxf(p0[rr], p1[rr]), p2[rr]);
    g_t2i[c * BATCH + b] = s * (1.0f / NR);
}

// ===== per-row cross-entropy (one warp per row, 192 rows) =====
__global__ void fg_rowce_kernel()
{
    const int wid = threadIdx.x >> 5;
    const int lid = threadIdx.x & 31;
    const int row = blockIdx.x * 32 + wid;
    if (row >= 2 * BATCH) return;
    const int label = (row < BATCH) ? row : row - BATCH;
    const float* base = (row < BATCH) ? &g_i2t[row * BATCH] : &g_t2i[(row - BATCH) * BATCH];

    float v0 = base[lid], v1 = base[lid + 32], v2 = base[lid + 64];
    float m = fmaxf(v0, fmaxf(v1, v2));
#pragma unroll
    for (int off = 16; off > 0; off >>= 1)
        m = fmaxf(m, __shfl_xor_sync(0xFFFFFFFFu, m, off));
    float s = expf(v0 - m) + expf(v1 - m) + expf(v2 - m);
#pragma unroll
    for (int off = 16; off > 0; off >>= 1)
        s += __shfl_xor_sync(0xFFFFFFFFu, s, off);
    float lse = m + logf(s);
    int slot = label >> 5, src = label & 31;
    float mine = (slot == 0) ? v0 : ((slot == 1) ? v1 : v2);
    float dval = __shfl_sync(0xFFFFFFFFu, mine, src);
    if (lid == 0) g_contrib[row] = lse - dval;
}

__global__ void fg_final_kernel(float* __restrict__ out)
{
    __shared__ float sred[192];
    const int t = threadIdx.x;
    sred[t] = g_contrib[t];
    __syncthreads();
    if (t == 0) {
        float s = 0.f;
        for (int i = 0; i < 2 * BATCH; i++) s += sred[i];
        out[0] = s * (0.5f / BATCH);
    }
}

extern "C" void kernel_launch(void* const* d_in, const int* in_sizes, int n_in,
                              void* d_out, int out_size)
{
    const float* img;
    const float* txt;
    if (in_sizes[0] > in_sizes[1]) { img = (const float*)d_in[0]; txt = (const float*)d_in[1]; }
    else                           { img = (const float*)d_in[1]; txt = (const float*)d_in[0]; }
    float* out = (float*)d_out;

    constexpr int STAGE = 2 * (2 * NPAD * ROWB);   // 25600 (B only)
    constexpr int SMEM  = 3 * STAGE + 1024;        // 77824 -> 2 CTAs/SM

    static int configured = 0;
    if (!configured) {
        cudaFuncSetAttribute(fg_mma_kernel<false>, cudaFuncAttributeMaxDynamicSharedMemorySize, SMEM);
        cudaFuncSetAttribute(fg_mma_kernel<true>,  cudaFuncAttributeMaxDynamicSharedMemorySize, SMEM);
        configured = 1;
    }

    // bf16 hi/lo split of both inputs
    {
        __nv_bfloat16 *ib0, *ib1, *tb0, *tb1;
        cudaGetSymbolAddress((void**)&ib0, g_ib0);
        cudaGetSymbolAddress((void**)&ib1, g_ib1);
        cudaGetSymbolAddress((void**)&tb0, g_tb0);
        cudaGetSymbolAddress((void**)&tb1, g_tb1);
        int ni = BATCH * NQ * DIM, nt = BATCH * NR * DIM;
        fg_split_kernel<<<(ni + 255) / 256, 256>>>(img, ib0, ib1, ni);
        fg_split_kernel<<<(nt + 255) / 256, 256>>>(txt, tb0, tb1, nt);
    }

    // m-tiles 0,1: rows 0-95, 96-191 (all valid).
    fg_mma_kernel<false><<<dim3(BATCH, BATCH / 2, 2), 128, SMEM>>>(0);
    // tail: rows 192-195 of all images, compacted 4 rows/image x 24 images/tile.
    fg_mma_kernel<true><<<dim3(4, BATCH / 2, 1), 128, SMEM>>>(2);
    fg_combine_kernel<<<BATCH, BATCH>>>();
    fg_rowce_kernel<<<6, 1024>>>();
    fg_final_kernel<<<1, 192>>>(out);
}

// round 15
// speedup vs baseline: 1.1710x; 1.1517x over previous
#include <cuda_runtime.h>
#include <cuda_bf16.h>
#include <cstdint>
#include <math.h>

#define BATCH 96
#define NQ 196
#define NR 77
#define DIM 512
#define KC 32                  // k elements per chunk
#define NCHUNK (DIM / KC)      // 16
#define NPAD 80
#define ROWB 80                // row stride bytes (64 data + 16 pad, conflict-free)
#define NTILES 3               // m-tiles: 96 + 96 + (compacted 4-row tail)

// ---------------- device scratch ----------------
__device__ __nv_bfloat16 g_ib0[BATCH * NQ * DIM];
__device__ __nv_bfloat16 g_ib1[BATCH * NQ * DIM];
__device__ __nv_bfloat16 g_tb0[BATCH * NR * DIM];
__device__ __nv_bfloat16 g_tb1[BATCH * NR * DIM];
__device__ float g_rowsum_part[NTILES * BATCH * BATCH];          // [mt][b][c]
__device__ float g_colmax_part[NTILES * BATCH * BATCH * NPAD];   // [mt][c][b][r]
__device__ float g_i2t[BATCH * BATCH];
__device__ float g_t2i[BATCH * BATCH];
__device__ float g_contrib[2 * BATCH];

// ---------------- PTX helpers (base sm_103 ISA only) ----------------
__device__ __forceinline__ uint32_t smem_u32(const void* p) {
    uint32_t a;
    asm("{ .reg .u64 t; cvta.to.shared.u64 t, %1; cvt.u32.u64 %0, t; }" : "=r"(a) : "l"(p));
    return a;
}
#define CP_ASYNC16(sa, gp, sz) \
    asm volatile("cp.async.cg.shared.global [%0], [%1], 16, %2;" \
        :: "r"(sa), "l"(gp), "r"(sz) : "memory")
#define CP_COMMIT()  asm volatile("cp.async.commit_group;" ::: "memory")
#define CP_WAIT1()   asm volatile("cp.async.wait_group 1;" ::: "memory")

#define LDSM_X4(r0, r1, r2, r3, a) \
    asm volatile("ldmatrix.sync.aligned.m8n8.x4.shared.b16 {%0,%1,%2,%3}, [%4];" \
        : "=r"(r0), "=r"(r1), "=r"(r2), "=r"(r3) : "r"(a))

#define MMA_BF16(d, a0, a1, a2, a3, b0, b1) \
    asm volatile("mma.sync.aligned.m16n8k16.row.col.f32.bf16.bf16.f32 " \
        "{%0,%1,%2,%3}, {%4,%5,%6,%7}, {%8,%9}, {%0,%1,%2,%3};" \
        : "+f"((d)[0]), "+f"((d)[1]), "+f"((d)[2]), "+f"((d)[3]) \
        : "r"(a0), "r"(a1), "r"(a2), "r"(a3), "r"(b0), "r"(b1))

// ===== precompute: split fp32 into bf16 hi (b0) and residual (b1) =====
__global__ void fg_split_kernel(const float* __restrict__ src,
                                __nv_bfloat16* __restrict__ b0,
                                __nv_bfloat16* __restrict__ b1, int n)
{
    int i = blockIdx.x * blockDim.x + threadIdx.x;
    if (i < n) {
        float x = src[i];
        __nv_bfloat16 h = __float2bfloat16(x);
        b0[i] = h;
        b1[i] = __float2bfloat16(x - __bfloat162float(h));
    }
}

// ======================================================================
// bf16x2 (3-pass) MMA kernel. CTA tile: 96 x 160 (TWO texts).
// Warps: 2 (M) x 2 (N); each N-warp owns ONE FULL text (80 cols).
// Single merged grid (96, 48, 3):
//   z = 0,1 : main planes — blockIdx.x = image, rows z*96..z*96+95.
//   z = 2   : compacted tail plane — only bx<4 active; row r maps to
//             image bx*24 + r/4, token 192 + r%4 (4-row tails of 24 images).
// Tail CTAs interleave with main waves, hiding the tail cost entirely.
// ======================================================================
__global__ __launch_bounds__(128, 2) void fg_mma_kernel()
{
    constexpr int MROWS = 96;
    constexpr int MWARPS = 2;
    constexpr int NT   = 128;
    constexpr int MW   = 48;
    constexpr int MF   = 3;
    constexpr int A_SZ = MROWS * ROWB;       // per part
    constexpr int B_SZ = 2 * NPAD * ROWB;    // 12800 per part (two texts)
    constexpr int STAGE = 2 * A_SZ + 2 * B_SZ;

    const bool TAIL = (blockIdx.z == 2);
    const int bx = blockIdx.x;       // image (main) or tile (tail)
    if (TAIL && bx >= 4) return;     // inactive tail CTAs exit immediately

    extern __shared__ char smem_raw[];
    __shared__ float scmax[MWARPS][2][NPAD];
    __shared__ float swsum[NT / 32];

    const uint32_t raw_u  = smem_u32(smem_raw);
    const uint32_t tile_u = (raw_u + 1023u) & ~1023u;

    const int tid = threadIdx.x;
    const int wid = tid >> 5;
    const int lid = tid & 31;
    const int wn = wid & 1;           // text within pair
    const int wm = wid >> 1;          // 0..1
    const int g  = lid >> 3;
    const int r  = lid & 7;

    const int cg   = blockIdx.y;
    const int mt   = blockIdx.z;      // 0,1 main tiles; 2 = tail tile

    const size_t Abase = TAIL ? 0 : ((size_t)bx * NQ + mt * 96) * DIM;
    const size_t Tbase = (size_t)(cg * 2) * NR * DIM;

    float acc[MF][10][4];
#pragma unroll
    for (int mf = 0; mf < MF; ++mf)
#pragma unroll
        for (int fn = 0; fn < 10; ++fn)
#pragma unroll
            for (int cc = 0; cc < 4; ++cc) acc[mf][fn][cc] = 0.0f;

    // ---------------- staging ----------------
    auto stage = [&](int ci, int buf) {
        const int k0 = ci * KC;
        const uint32_t base = tile_u + buf * STAGE;
        // A: 96 rows x 4 slots x {b0,b1} = 768 ops
#pragma unroll
        for (int i = 0; i < (MROWS * 8) / NT; ++i) {
            int idx = tid + i * NT;
            int arr = (idx >= MROWS * 4) ? 1 : 0;
            int rem = idx - arr * MROWS * 4;
            int row = rem >> 2, u = rem & 3;
            size_t off;
            if (TAIL) {
                int img = bx * 24 + (row >> 2);
                int q   = 192 + (row & 3);
                off = ((size_t)img * NQ + q) * DIM + k0 + u * 8;
            } else {
                off = Abase + (size_t)row * DIM + k0 + u * 8;
            }
            const __nv_bfloat16* sp = (arr ? g_ib1 : g_ib0) + off;
            uint32_t sa = base + arr * A_SZ + row * ROWB + u * 16;
            CP_ASYNC16(sa, sp, 16u);
        }
        // B: 160 rows (2 texts x 80) x 4 slots x {b0,b1} = 1280 ops
#pragma unroll
        for (int i = 0; i < 1280 / NT; ++i) {
            int idx = tid + i * NT;
            int arr = (idx >= 640) ? 1 : 0;
            int rem = idx - arr * 640;
            int row = rem >> 2, u = rem & 3;
            int tg = row / NPAD, rr = row - tg * NPAD;
            int crr = rr < NR ? rr : 0;
            const __nv_bfloat16* sp = (arr ? g_tb1 : g_tb0) + Tbase + ((size_t)tg * NR + crr) * DIM + k0 + u * 8;
            uint32_t sz = (rr < NR) ? 16u : 0u;
            uint32_t sa = base + 2 * A_SZ + arr * B_SZ + row * ROWB + u * 16;
            CP_ASYNC16(sa, sp, sz);
        }
        CP_COMMIT();
    };

    stage(0, 0);
    stage(1, 1);

    // per-lane ldmatrix offsets (validated lane maps)
    const uint32_t a_row = (uint32_t)((wm * MW + (g & 1) * 8 + r) * ROWB);
    const uint32_t a_ub  = (uint32_t)(g >> 1);
    const uint32_t b_row = (uint32_t)((wn * NPAD + (g >> 1) * 8 + r) * ROWB);
    const uint32_t b_ub  = (uint32_t)(g & 1);

    // ---------------- main loop ----------------
    for (int ci = 0; ci < NCHUNK; ++ci) {
        const int buf = ci & 1;
        CP_WAIT1();
        __syncthreads();

        const uint32_t sA = tile_u + buf * STAGE;
        const uint32_t sB = sA + 2 * A_SZ;

#pragma unroll
        for (int ks = 0; ks < 2; ++ks) {
            uint32_t a0[MF][4], a1[MF][4];
            const uint32_t a_ch = (uint32_t)(ks * 32) + a_ub * 16;
#pragma unroll
            for (int mf = 0; mf < MF; ++mf) {
                uint32_t ad = sA + a_row + (uint32_t)(mf * 16 * ROWB) + a_ch;
                LDSM_X4(a0[mf][0], a0[mf][1], a0[mf][2], a0[mf][3], ad);
                LDSM_X4(a1[mf][0], a1[mf][1], a1[mf][2], a1[mf][3], ad + A_SZ);
            }
            const uint32_t b_ch = (uint32_t)(ks * 32) + b_ub * 16;
#pragma unroll
            for (int p = 0; p < 5; ++p) {
                uint32_t bh[4], bl[4];
                uint32_t bd = sB + b_row + (uint32_t)(p * 16 * ROWB) + b_ch;
                LDSM_X4(bh[0], bh[1], bh[2], bh[3], bd);
                LDSM_X4(bl[0], bl[1], bl[2], bl[3], bd + B_SZ);
#pragma unroll
                for (int mf = 0; mf < MF; ++mf)
                    MMA_BF16(acc[mf][2 * p],     a0[mf][0], a0[mf][1], a0[mf][2], a0[mf][3], bh[0], bh[1]);
#pragma unroll
                for (int mf = 0; mf < MF; ++mf)
                    MMA_BF16(acc[mf][2 * p + 1], a0[mf][0], a0[mf][1], a0[mf][2], a0[mf][3], bh[2], bh[3]);
#pragma unroll
                for (int mf = 0; mf < MF; ++mf)
                    MMA_BF16(acc[mf][2 * p],     a0[mf][0], a0[mf][1], a0[mf][2], a0[mf][3], bl[0], bl[1]);
#pragma unroll
                for (int mf = 0; mf < MF; ++mf)
                    MMA_BF16(acc[mf][2 * p + 1], a0[mf][0], a0[mf][1], a0[mf][2], a0[mf][3], bl[2], bl[3]);
#pragma unroll
                for (int mf = 0; mf < MF; ++mf)
                    MMA_BF16(acc[mf][2 * p],     a1[mf][0], a1[mf][1], a1[mf][2], a1[mf][3], bh[0], bh[1]);
#pragma unroll
                for (int mf = 0; mf < MF; ++mf)
                    MMA_BF16(acc[mf][2 * p + 1], a1[mf][0], a1[mf][1], a1[mf][2], a1[mf][3], bh[2], bh[3]);
            }
        }

        __syncthreads();
        if (ci + 2 < NCHUNK) stage(ci + 2, buf);
        else                 CP_COMMIT();   // keep group parity
    }

    // ---------------- epilogue ----------------
    // acc (mf, fn, cc): row_l = wm*48 + mf*16 + (cc>=2)*8 + lid/4
    //                   col   = fn*8 + 2*(lid&3) + (cc&1)   (within text wn)
    const int c0b = 2 * (lid & 3);
    const int cdx = cg * 2 + wn;      // text index

    if (!TAIL) {
        float rsum = 0.0f;
#pragma unroll
        for (int mf = 0; mf < MF; ++mf) {
#pragma unroll
            for (int h = 0; h < 2; ++h) {
                float m = -INFINITY;
#pragma unroll
                for (int fn = 0; fn < 10; ++fn) {
                    int col = fn * 8 + c0b;
                    if (col < NR)     m = fmaxf(m, acc[mf][fn][h * 2 + 0]);
                    if (col + 1 < NR) m = fmaxf(m, acc[mf][fn][h * 2 + 1]);
                }
                m = fmaxf(m, __shfl_xor_sync(0xFFFFFFFFu, m, 1));
                m = fmaxf(m, __shfl_xor_sync(0xFFFFFFFFu, m, 2));
                if ((lid & 3) == 0) rsum += m;
            }
        }
#pragma unroll
        for (int off = 16; off > 0; off >>= 1)
            rsum += __shfl_xor_sync(0xFFFFFFFFu, rsum, off);
        if (lid == 0) swsum[wid] = rsum;

#pragma unroll
        for (int fn = 0; fn < 10; ++fn) {
#pragma unroll
            for (int cb = 0; cb < 2; ++cb) {
                float m = -INFINITY;
#pragma unroll
                for (int mf = 0; mf < MF; ++mf)
#pragma unroll
                    for (int h = 0; h < 2; ++h)
                        m = fmaxf(m, acc[mf][fn][h * 2 + cb]);
                m = fmaxf(m, __shfl_xor_sync(0xFFFFFFFFu, m, 4));
                m = fmaxf(m, __shfl_xor_sync(0xFFFFFFFFu, m, 8));
                m = fmaxf(m, __shfl_xor_sync(0xFFFFFFFFu, m, 16));
                if (lid < 4) scmax[wm][wn][fn * 8 + 2 * lid + cb] = m;
            }
        }
        __syncthreads();

        if (tid < 2) {
            float s = swsum[tid];
#pragma unroll
            for (int w = 1; w < MWARPS; ++w) s += swsum[w * 2 + tid];
            g_rowsum_part[((size_t)mt * BATCH + bx) * BATCH + cg * 2 + tid] = s;
        }
        for (int idx = tid; idx < 2 * NPAD; idx += NT) {
            int wn2 = idx / NPAD, col = idx - wn2 * NPAD;
            float m = scmax[0][wn2][col];
#pragma unroll
            for (int w = 1; w < MWARPS; ++w) m = fmaxf(m, scmax[w][wn2][col]);
            int c = cg * 2 + wn2;
            g_colmax_part[(((size_t)mt * BATCH + c) * BATCH + bx) * NPAD + col] = m;
        }
    } else {
        // -------- tail epilogue: per-4-row-group (= per image) reductions --------
#pragma unroll
        for (int mf = 0; mf < MF; ++mf) {
#pragma unroll
            for (int h = 0; h < 2; ++h) {
                float m = -INFINITY;
#pragma unroll
                for (int fn = 0; fn < 10; ++fn) {
                    int col = fn * 8 + c0b;
                    if (col < NR)     m = fmaxf(m, acc[mf][fn][h * 2 + 0]);
                    if (col + 1 < NR) m = fmaxf(m, acc[mf][fn][h * 2 + 1]);
                }
                m = fmaxf(m, __shfl_xor_sync(0xFFFFFFFFu, m, 1));
                m = fmaxf(m, __shfl_xor_sync(0xFFFFFFFFu, m, 2));
                m += __shfl_xor_sync(0xFFFFFFFFu, m, 4);
                m += __shfl_xor_sync(0xFFFFFFFFu, m, 8);
                if ((lid & 15) == 0) {
                    int group = mf * 4 + h * 2 + (lid >> 4);
                    int img = bx * 24 + wm * 12 + group;
                    g_rowsum_part[((size_t)mt * BATCH + img) * BATCH + cdx] = m;
                }
            }
        }
#pragma unroll
        for (int mf = 0; mf < MF; ++mf) {
#pragma unroll
            for (int h = 0; h < 2; ++h) {
#pragma unroll
                for (int fn = 0; fn < 10; ++fn) {
#pragma unroll
                    for (int cb = 0; cb < 2; ++cb) {
                        float v = acc[mf][fn][h * 2 + cb];
                        v = fmaxf(v, __shfl_xor_sync(0xFFFFFFFFu, v, 4));
                        v = fmaxf(v, __shfl_xor_sync(0xFFFFFFFFu, v, 8));
                        if (((lid >> 2) & 3) == 0) {
                            int group = mf * 4 + h * 2 + (lid >> 4);
                            int img = bx * 24 + wm * 12 + group;
                            int col = fn * 8 + c0b + cb;
                            if (col < NR)
                                g_colmax_part[(((size_t)mt * BATCH + cdx) * BATCH + img) * NPAD + col] = v;
                        }
                    }
                }
            }
        }
    }
}

// ===== combine partial tiles into logit matrices =====
__global__ void fg_combine_kernel()
{
    const int c = blockIdx.x;    // 96
    const int b = threadIdx.x;   // 96
    float rs = 0.f;
#pragma unroll
    for (int t = 0; t < NTILES; ++t)
        rs += g_rowsum_part[((size_t)t * BATCH + b) * BATCH + c];
    g_i2t[b * BATCH + c] = rs * (1.0f / NQ);

    const float* p0 = &g_colmax_part[(((size_t)0 * BATCH + c) * BATCH + b) * NPAD];
    const float* p1 = &g_colmax_part[(((size_t)1 * BATCH + c) * BATCH + b) * NPAD];
    const float* p2 = &g_colmax_part[(((size_t)2 * BATCH + c) * BATCH + b) * NPAD];
    float s = 0.f;
#pragma unroll
    for (int rr = 0; rr < NR; ++rr) s += fmaxf(fmaxf(p0[rr], p1[rr]), p2[rr]);
    g_t2i[c * BATCH + b] = s * (1.0f / NR);
}

// ===== per-row cross-entropy (one warp per row, 192 rows) =====
__global__ void fg_rowce_kernel()
{
    const int wid = threadIdx.x >> 5;
    const int lid = threadIdx.x & 31;
    const int row = blockIdx.x * 32 + wid;
    if (row >= 2 * BATCH) return;
    const int label = (row < BATCH) ? row : row - BATCH;
    const float* base = (row < BATCH) ? &g_i2t[row * BATCH] : &g_t2i[(row - BATCH) * BATCH];

    float v0 = base[lid], v1 = base[lid + 32], v2 = base[lid + 64];
    float m = fmaxf(v0, fmaxf(v1, v2));
#pragma unroll
    for (int off = 16; off > 0; off >>= 1)
        m = fmaxf(m, __shfl_xor_sync(0xFFFFFFFFu, m, off));
    float s = expf(v0 - m) + expf(v1 - m) + expf(v2 - m);
#pragma unroll
    for (int off = 16; off > 0; off >>= 1)
        s += __shfl_xor_sync(0xFFFFFFFFu, s, off);
    float lse = m + logf(s);
    int slot = label >> 5, src = label & 31;
    float mine = (slot == 0) ? v0 : ((slot == 1) ? v1 : v2);
    float dval = __shfl_sync(0xFFFFFFFFu, mine, src);
    if (lid == 0) g_contrib[row] = lse - dval;
}

__global__ void fg_final_kernel(float* __restrict__ out)
{
    __shared__ float sred[192];
    const int t = threadIdx.x;
    sred[t] = g_contrib[t];
    __syncthreads();
    if (t == 0) {
        float s = 0.f;
        for (int i = 0; i < 2 * BATCH; i++) s += sred[i];
        out[0] = s * (0.5f / BATCH);
    }
}

extern "C" void kernel_launch(void* const* d_in, const int* in_sizes, int n_in,
                              void* d_out, int out_size)
{
    const float* img;
    const float* txt;
    if (in_sizes[0] > in_sizes[1]) { img = (const float*)d_in[0]; txt = (const float*)d_in[1]; }
    else                           { img = (const float*)d_in[1]; txt = (const float*)d_in[0]; }
    float* out = (float*)d_out;

    constexpr int STAGE = 2 * (96 * ROWB) + 2 * (2 * NPAD * ROWB);   // 40960
    constexpr int SMEM  = 2 * STAGE + 1024;   // 82944 -> 2 CTAs/SM

    static int configured = 0;
    if (!configured) {
        cudaFuncSetAttribute(fg_mma_kernel, cudaFuncAttributeMaxDynamicSharedMemorySize, SMEM);
        configured = 1;
    }

    // bf16 hi/lo split of both inputs
    {
        __nv_bfloat16 *ib0, *ib1, *tb0, *tb1;
        cudaGetSymbolAddress((void**)&ib0, g_ib0);
        cudaGetSymbolAddress((void**)&ib1, g_ib1);
        cudaGetSymbolAddress((void**)&tb0, g_tb0);
        cudaGetSymbolAddress((void**)&tb1, g_tb1);
        int ni = BATCH * NQ * DIM, nt = BATCH * NR * DIM;
        fg_split_kernel<<<(ni + 255) / 256, 256>>>(img, ib0, ib1, ni);
        fg_split_kernel<<<(nt + 255) / 256, 256>>>(txt, tb0, tb1, nt);
    }

    // merged grid: z=0,1 main m-tiles (rows 0-95, 96-191); z=2 compacted tail.
    fg_mma_kernel<<<dim3(BATCH, BATCH / 2, 3), 128, SMEM>>>();
    fg_combine_kernel<<<BATCH, BATCH>>>();
    fg_rowce_kernel<<<6, 1024>>>();
    fg_final_kernel<<<1, 192>>>(out);
}

// round 17
// speedup vs baseline: 1.5886x; 1.3566x over previous
#include <cuda_runtime.h>
#include <cuda_fp16.h>
#include <cstdint>
#include <math.h>

#define BATCH 96
#define NQ 196
#define NR 77
#define DIM 512
#define KC 32                  // k elements per chunk
#define NCHUNK (DIM / KC)      // 16
#define NPAD 80
#define ROWB 80                // row stride bytes (64 data + 16 pad, conflict-free)
#define NTILES 3               // m-tiles: 96 + 96 + (compacted 4-row tail)

// ---------------- device scratch ----------------
__device__ __half g_ia[BATCH * NQ * DIM];     // image, single fp16
__device__ __half g_tb0[BATCH * NR * DIM];    // text hi
__device__ __half g_tb1[BATCH * NR * DIM];    // text lo (residual)
__device__ float g_rowsum_part[NTILES * BATCH * BATCH];          // [mt][b][c]
__device__ float g_colmax_part[NTILES * BATCH * BATCH * NPAD];   // [mt][c][b][r]
__device__ float g_i2t[BATCH * BATCH];
__device__ float g_t2i[BATCH * BATCH];
__device__ float g_contrib[2 * BATCH];

// ---------------- PTX helpers (base sm_103 ISA only) ----------------
__device__ __forceinline__ uint32_t smem_u32(const void* p) {
    uint32_t a;
    asm("{ .reg .u64 t; cvta.to.shared.u64 t, %1; cvt.u32.u64 %0, t; }" : "=r"(a) : "l"(p));
    return a;
}
#define CP_ASYNC16(sa, gp, sz) \
    asm volatile("cp.async.cg.shared.global [%0], [%1], 16, %2;" \
        :: "r"(sa), "l"(gp), "r"(sz) : "memory")
#define CP_COMMIT()  asm volatile("cp.async.commit_group;" ::: "memory")
#define CP_WAIT1()   asm volatile("cp.async.wait_group 1;" ::: "memory")

#define LDSM_X4(r0, r1, r2, r3, a) \
    asm volatile("ldmatrix.sync.aligned.m8n8.x4.shared.b16 {%0,%1,%2,%3}, [%4];" \
        : "=r"(r0), "=r"(r1), "=r"(r2), "=r"(r3) : "r"(a))

#define MMA_F16(d, a0, a1, a2, a3, b0, b1) \
    asm volatile("mma.sync.aligned.m16n8k16.row.col.f32.f16.f16.f32 " \
        "{%0,%1,%2,%3}, {%4,%5,%6,%7}, {%8,%9}, {%0,%1,%2,%3};" \
        : "+f"((d)[0]), "+f"((d)[1]), "+f"((d)[2]), "+f"((d)[3]) \
        : "r"(a0), "r"(a1), "r"(a2), "r"(a3), "r"(b0), "r"(b1))

// ===== precompute: image -> single fp16 =====
__global__ void fg_half_kernel(const float* __restrict__ src,
                               __half* __restrict__ dst, int n)
{
    int i = blockIdx.x * blockDim.x + threadIdx.x;
    if (i < n) dst[i] = __float2half(src[i]);
}

// ===== precompute: text -> fp16 hi + fp16 residual =====
__global__ void fg_split_kernel(const float* __restrict__ src,
                                __half* __restrict__ h0,
                                __half* __restrict__ h1, int n)
{
    int i = blockIdx.x * blockDim.x + threadIdx.x;
    if (i < n) {
        float x = src[i];
        __half h = __float2half(x);
        h0[i] = h;
        h1[i] = __float2half(x - __half2float(h));
    }
}

// ======================================================================
// fp16 2-pass MMA kernel: S = a * (t0 + t1), a single fp16, text split.
// CTA tile: 96 x 160 (TWO texts). Warps: 2 (M) x 2 (N); each N-warp owns
// ONE FULL text (80 cols).
// TAIL=false: blockIdx.x = image, rows mt*96..mt*96+95 of that image.
// TAIL=true : blockIdx.x = tile (0..3); row r -> image tile*24 + r/4,
//             token 192 + r%4  (compacted 4-row tails of 24 images).
// ======================================================================
template <bool TAIL>
__global__ __launch_bounds__(128, 2) void fg_mma_kernel(int mt_base)
{
    constexpr int MROWS = 96;
    constexpr int MWARPS = 2;
    constexpr int NT   = 128;
    constexpr int MW   = 48;
    constexpr int MF   = 3;
    constexpr int A_SZ = MROWS * ROWB;       // 7680 (single part)
    constexpr int B_SZ = 2 * NPAD * ROWB;    // 12800 per part (two texts)
    constexpr int STAGE = A_SZ + 2 * B_SZ;   // 33280

    extern __shared__ char smem_raw[];
    __shared__ float scmax[MWARPS][2][NPAD];
    __shared__ float swsum[NT / 32];

    const uint32_t raw_u  = smem_u32(smem_raw);
    const uint32_t tile_u = (raw_u + 1023u) & ~1023u;

    const int tid = threadIdx.x;
    const int wid = tid >> 5;
    const int lid = tid & 31;
    const int wn = wid & 1;           // text within pair
    const int wm = wid >> 1;          // 0..1
    const int g  = lid >> 3;
    const int r  = lid & 7;

    const int bx   = blockIdx.x;      // image (main) or tile (tail)
    const int cg   = blockIdx.y;
    const int mt   = mt_base + blockIdx.z;

    const size_t Abase = TAIL ? 0 : ((size_t)bx * NQ + mt * 96) * DIM;
    const size_t Tbase = (size_t)(cg * 2) * NR * DIM;

    float acc[MF][10][4];
#pragma unroll
    for (int mf = 0; mf < MF; ++mf)
#pragma unroll
        for (int fn = 0; fn < 10; ++fn)
#pragma unroll
            for (int cc = 0; cc < 4; ++cc) acc[mf][fn][cc] = 0.0f;

    // ---------------- staging ----------------
    auto stage = [&](int ci, int buf) {
        const int k0 = ci * KC;
        const uint32_t base = tile_u + buf * STAGE;
        // A: 96 rows x 4 slots (single part) = 384 ops
#pragma unroll
        for (int i = 0; i < (MROWS * 4) / NT; ++i) {
            int idx = tid + i * NT;
            int row = idx >> 2, u = idx & 3;
            size_t off;
            if (TAIL) {
                int img = bx * 24 + (row >> 2);
                int q   = 192 + (row & 3);
                off = ((size_t)img * NQ + q) * DIM + k0 + u * 8;
            } else {
                off = Abase + (size_t)row * DIM + k0 + u * 8;
            }
            uint32_t sa = base + row * ROWB + u * 16;
            CP_ASYNC16(sa, g_ia + off, 16u);
        }
        // B: 160 rows (2 texts x 80) x 4 slots x {t0,t1} = 1280 ops
#pragma unroll
        for (int i = 0; i < 1280 / NT; ++i) {
            int idx = tid + i * NT;
            int arr = (idx >= 640) ? 1 : 0;
            int rem = idx - arr * 640;
            int row = rem >> 2, u = rem & 3;
            int tg = row / NPAD, rr = row - tg * NPAD;
            int crr = rr < NR ? rr : 0;
            const __half* sp = (arr ? g_tb1 : g_tb0) + Tbase + ((size_t)tg * NR + crr) * DIM + k0 + u * 8;
            uint32_t sz = (rr < NR) ? 16u : 0u;
            uint32_t sa = base + A_SZ + arr * B_SZ + row * ROWB + u * 16;
            CP_ASYNC16(sa, sp, sz);
        }
        CP_COMMIT();
    };

    stage(0, 0);
    stage(1, 1);

    // per-lane ldmatrix offsets (validated lane maps)
    const uint32_t a_row = (uint32_t)((wm * MW + (g & 1) * 8 + r) * ROWB);
    const uint32_t a_ub  = (uint32_t)(g >> 1);
    const uint32_t b_row = (uint32_t)((wn * NPAD + (g >> 1) * 8 + r) * ROWB);
    const uint32_t b_ub  = (uint32_t)(g & 1);

    // ---------------- main loop ----------------
    for (int ci = 0; ci < NCHUNK; ++ci) {
        const int buf = ci & 1;
        CP_WAIT1();
        __syncthreads();

        const uint32_t sA = tile_u + buf * STAGE;
        const uint32_t sB = sA + A_SZ;

#pragma unroll
        for (int ks = 0; ks < 2; ++ks) {
            uint32_t a[MF][4];
            const uint32_t a_ch = (uint32_t)(ks * 32) + a_ub * 16;
#pragma unroll
            for (int mf = 0; mf < MF; ++mf) {
                uint32_t ad = sA + a_row + (uint32_t)(mf * 16 * ROWB) + a_ch;
                LDSM_X4(a[mf][0], a[mf][1], a[mf][2], a[mf][3], ad);
            }
            const uint32_t b_ch = (uint32_t)(ks * 32) + b_ub * 16;
#pragma unroll
            for (int p = 0; p < 5; ++p) {
                uint32_t bh[4], bl[4];
                uint32_t bd = sB + b_row + (uint32_t)(p * 16 * ROWB) + b_ch;
                LDSM_X4(bh[0], bh[1], bh[2], bh[3], bd);
                LDSM_X4(bl[0], bl[1], bl[2], bl[3], bd + B_SZ);
                // pass 1: a * t0
#pragma unroll
                for (int mf = 0; mf < MF; ++mf)
                    MMA_F16(acc[mf][2 * p],     a[mf][0], a[mf][1], a[mf][2], a[mf][3], bh[0], bh[1]);
#pragma unroll
                for (int mf = 0; mf < MF; ++mf)
                    MMA_F16(acc[mf][2 * p + 1], a[mf][0], a[mf][1], a[mf][2], a[mf][3], bh[2], bh[3]);
                // pass 2: a * t1
#pragma unroll
                for (int mf = 0; mf < MF; ++mf)
                    MMA_F16(acc[mf][2 * p],     a[mf][0], a[mf][1], a[mf][2], a[mf][3], bl[0], bl[1]);
#pragma unroll
                for (int mf = 0; mf < MF; ++mf)
                    MMA_F16(acc[mf][2 * p + 1], a[mf][0], a[mf][1], a[mf][2], a[mf][3], bl[2], bl[3]);
            }
        }

        __syncthreads();
        if (ci + 2 < NCHUNK) stage(ci + 2, buf);
        else                 CP_COMMIT();   // keep group parity
    }

    // ---------------- epilogue ----------------
    // acc (mf, fn, cc): row_l = wm*48 + mf*16 + (cc>=2)*8 + lid/4
    //                   col   = fn*8 + 2*(lid&3) + (cc&1)   (within text wn)
    const int c0b = 2 * (lid & 3);
    const int cdx = cg * 2 + wn;      // text index

    if (!TAIL) {
        float rsum = 0.0f;
#pragma unroll
        for (int mf = 0; mf < MF; ++mf) {
#pragma unroll
            for (int h = 0; h < 2; ++h) {
                float m = -INFINITY;
#pragma unroll
                for (int fn = 0; fn < 10; ++fn) {
                    int col = fn * 8 + c0b;
                    if (col < NR)     m = fmaxf(m, acc[mf][fn][h * 2 + 0]);
                    if (col + 1 < NR) m = fmaxf(m, acc[mf][fn][h * 2 + 1]);
                }
                m = fmaxf(m, __shfl_xor_sync(0xFFFFFFFFu, m, 1));
                m = fmaxf(m, __shfl_xor_sync(0xFFFFFFFFu, m, 2));
                if ((lid & 3) == 0) rsum += m;
            }
        }
#pragma unroll
        for (int off = 16; off > 0; off >>= 1)
            rsum += __shfl_xor_sync(0xFFFFFFFFu, rsum, off);
        if (lid == 0) swsum[wid] = rsum;

#pragma unroll
        for (int fn = 0; fn < 10; ++fn) {
#pragma unroll
            for (int cb = 0; cb < 2; ++cb) {
                float m = -INFINITY;
#pragma unroll
                for (int mf = 0; mf < MF; ++mf)
#pragma unroll
                    for (int h = 0; h < 2; ++h)
                        m = fmaxf(m, acc[mf][fn][h * 2 + cb]);
                m = fmaxf(m, __shfl_xor_sync(0xFFFFFFFFu, m, 4));
                m = fmaxf(m, __shfl_xor_sync(0xFFFFFFFFu, m, 8));
                m = fmaxf(m, __shfl_xor_sync(0xFFFFFFFFu, m, 16));
                if (lid < 4) scmax[wm][wn][fn * 8 + 2 * lid + cb] = m;
            }
        }
        __syncthreads();

        if (tid < 2) {
            float s = swsum[tid];
#pragma unroll
            for (int w = 1; w < MWARPS; ++w) s += swsum[w * 2 + tid];
            g_rowsum_part[((size_t)mt * BATCH + bx) * BATCH + cg * 2 + tid] = s;
        }
        for (int idx = tid; idx < 2 * NPAD; idx += NT) {
            int wn2 = idx / NPAD, col = idx - wn2 * NPAD;
            float m = scmax[0][wn2][col];
#pragma unroll
            for (int w = 1; w < MWARPS; ++w) m = fmaxf(m, scmax[w][wn2][col]);
            int c = cg * 2 + wn2;
            g_colmax_part[(((size_t)mt * BATCH + c) * BATCH + bx) * NPAD + col] = m;
        }
    } else {
        // -------- tail epilogue: per-4-row-group (= per image) reductions --------
#pragma unroll
        for (int mf = 0; mf < MF; ++mf) {
#pragma unroll
            for (int h = 0; h < 2; ++h) {
                float m = -INFINITY;
#pragma unroll
                for (int fn = 0; fn < 10; ++fn) {
                    int col = fn * 8 + c0b;
                    if (col < NR)     m = fmaxf(m, acc[mf][fn][h * 2 + 0]);
                    if (col + 1 < NR) m = fmaxf(m, acc[mf][fn][h * 2 + 1]);
                }
                m = fmaxf(m, __shfl_xor_sync(0xFFFFFFFFu, m, 1));
                m = fmaxf(m, __shfl_xor_sync(0xFFFFFFFFu, m, 2));
                m += __shfl_xor_sync(0xFFFFFFFFu, m, 4);
                m += __shfl_xor_sync(0xFFFFFFFFu, m, 8);
                if ((lid & 15) == 0) {
                    int group = mf * 4 + h * 2 + (lid >> 4);
                    int img = bx * 24 + wm * 12 + group;
                    g_rowsum_part[((size_t)mt * BATCH + img) * BATCH + cdx] = m;
                }
            }
        }
#pragma unroll
        for (int mf = 0; mf < MF; ++mf) {
#pragma unroll
            for (int h = 0; h < 2; ++h) {
#pragma unroll
                for (int fn = 0; fn < 10; ++fn) {
#pragma unroll
                    for (int cb = 0; cb < 2; ++cb) {
                        float v = acc[mf][fn][h * 2 + cb];
                        v = fmaxf(v, __shfl_xor_sync(0xFFFFFFFFu, v, 4));
                        v = fmaxf(v, __shfl_xor_sync(0xFFFFFFFFu, v, 8));
                        if (((lid >> 2) & 3) == 0) {
                            int group = mf * 4 + h * 2 + (lid >> 4);
                            int img = bx * 24 + wm * 12 + group;
                            int col = fn * 8 + c0b + cb;
                            if (col < NR)
                                g_colmax_part[(((size_t)mt * BATCH + cdx) * BATCH + img) * NPAD + col] = v;
                        }
                    }
                }
            }
        }
    }
}

// ===== combine partial tiles into logit matrices =====
__global__ void fg_combine_kernel()
{
    const int c = blockIdx.x;    // 96
    const int b = threadIdx.x;   // 96
    float rs = 0.f;
#pragma unroll
    for (int t = 0; t < NTILES; ++t)
        rs += g_rowsum_part[((size_t)t * BATCH + b) * BATCH + c];
    g_i2t[b * BATCH + c] = rs * (1.0f / NQ);

    const float* p0 = &g_colmax_part[(((size_t)0 * BATCH + c) * BATCH + b) * NPAD];
    const float* p1 = &g_colmax_part[(((size_t)1 * BATCH + c) * BATCH + b) * NPAD];
    const float* p2 = &g_colmax_part[(((size_t)2 * BATCH + c) * BATCH + b) * NPAD];
    float s = 0.f;
#pragma unroll
    for (int rr = 0; rr < NR; ++rr) s += fmaxf(fmaxf(p0[rr], p1[rr]), p2[rr]);
    g_t2i[c * BATCH + b] = s * (1.0f / NR);
}

// ===== per-row cross-entropy (one warp per row, 192 rows) =====
__global__ void fg_rowce_kernel()
{
    const int wid = threadIdx.x >> 5;
    const int lid = threadIdx.x & 31;
    const int row = blockIdx.x * 32 + wid;
    if (row >= 2 * BATCH) return;
    const int label = (row < BATCH) ? row : row - BATCH;
    const float* base = (row < BATCH) ? &g_i2t[row * BATCH] : &g_t2i[(row - BATCH) * BATCH];

    float v0 = base[lid], v1 = base[lid + 32], v2 = base[lid + 64];
    float m = fmaxf(v0, fmaxf(v1, v2));
#pragma unroll
    for (int off = 16; off > 0; off >>= 1)
        m = fmaxf(m, __shfl_xor_sync(0xFFFFFFFFu, m, off));
    float s = expf(v0 - m) + expf(v1 - m) + expf(v2 - m);
#pragma unroll
    for (int off = 16; off > 0; off >>= 1)
        s += __shfl_xor_sync(0xFFFFFFFFu, s, off);
    float lse = m + logf(s);
    int slot = label >> 5, src = label & 31;
    float mine = (slot == 0) ? v0 : ((slot == 1) ? v1 : v2);
    float dval = __shfl_sync(0xFFFFFFFFu, mine, src);
    if (lid == 0) g_contrib[row] = lse - dval;
}

__global__ void fg_final_kernel(float* __restrict__ out)
{
    __shared__ float sred[192];
    const int t = threadIdx.x;
    sred[t] = g_contrib[t];
    __syncthreads();
    if (t == 0) {
        float s = 0.f;
        for (int i = 0; i < 2 * BATCH; i++) s += sred[i];
        out[0] = s * (0.5f / BATCH);
    }
}

extern "C" void kernel_launch(void* const* d_in, const int* in_sizes, int n_in,
                              void* d_out, int out_size)
{
    const float* img;
    const float* txt;
    if (in_sizes[0] > in_sizes[1]) { img = (const float*)d_in[0]; txt = (const float*)d_in[1]; }
    else                           { img = (const float*)d_in[1]; txt = (const float*)d_in[0]; }
    float* out = (float*)d_out;

    constexpr int STAGE = 96 * ROWB + 2 * (2 * NPAD * ROWB);   // 33280
    constexpr int SMEM  = 2 * STAGE + 1024;                    // 67584 -> 2 CTAs/SM

    static int configured = 0;
    if (!configured) {
        cudaFuncSetAttribute(fg_mma_kernel<false>, cudaFuncAttributeMaxDynamicSharedMemorySize, SMEM);
        cudaFuncSetAttribute(fg_mma_kernel<true>,  cudaFuncAttributeMaxDynamicSharedMemorySize, SMEM);
        configured = 1;
    }

    // image -> single fp16; text -> fp16 hi + fp16 residual
    {
        __half *ia, *tb0, *tb1;
        cudaGetSymbolAddress((void**)&ia,  g_ia);
        cudaGetSymbolAddress((void**)&tb0, g_tb0);
        cudaGetSymbolAddress((void**)&tb1, g_tb1);
        int ni = BATCH * NQ * DIM, nt = BATCH * NR * DIM;
        fg_half_kernel<<<(ni + 255) / 256, 256>>>(img, ia, ni);
        fg_split_kernel<<<(nt + 255) / 256, 256>>>(txt, tb0, tb1, nt);
    }

    // m-tiles 0,1: rows 0-95, 96-191 (all valid).
    fg_mma_kernel<false><<<dim3(BATCH, BATCH / 2, 2), 128, SMEM>>>(0);
    // tail: rows 192-195 of all images, compacted 4 rows/image x 24 images/tile.
    fg_mma_kernel<true><<<dim3(4, BATCH / 2, 1), 128, SMEM>>>(2);
    fg_combine_kernel<<<BATCH, BATCH>>>();
    fg_rowce_kernel<<<6, 1024>>>();
    fg_final_kernel<<<1, 192>>>(out);
}